// round 10
// baseline (speedup 1.0000x reference)
#include <cuda_runtime.h>
#include <cuda_bf16.h>
#include <cstdint>

#define N_NODES_C 50000
#define N_EDGES_C 800000

#define TPB_N 256          // node kernel: 8 warps
#define TPB_E 320          // edge kernel: 10 warps
#define NW_E 10
#define N_WT_EDGE (N_EDGES_C / 16)          // 50000 warp-tiles
#define N_WT_NODE (N_NODES_C / 16)          // 3125 warp-tiles

// Per-node layer-1 partials (scratch; no allocation allowed)
__device__ float g_P[(size_t)N_NODES_C * 128];   // nf@W1[0:64] + st@W1[160:192]
__device__ float g_Q[(size_t)N_NODES_C * 128];   // nf@W1[64:128]

// ---------------- edge kernel SMEM (bytes) ----------------
#define OFF_W1 0                          // kc=2, nc=16 : 16384
#define OFF_W2 16384                      // kc=8, nc=16 : 65536
#define OFF_W3 81920                      // kc=8, nc=8  : 32768
#define OFF_B1 114688                     // 128 f32
#define OFF_B2 115200                     // 128 f32
#define OFF_B3 115712                     // 64 f32
#define OFF_PQ 115968                     // 10 warps * 16 rows * 132 f32
#define PQ_STRIDE 132                     // mod 32 == 4 -> conflict-free frag reads
#define PQ_WARP_BYTES (16*PQ_STRIDE*4)    // 8448
#define EDGE_SMEM_BYTES (OFF_PQ + NW_E*PQ_WARP_BYTES)   // 200448

// ---------------- fused node kernel SMEM (bytes) ----------------
#define NOFF_BP  0
#define NOFF_BQ  49152
#define NOFF_BU1 81920
#define NOFF_BU2 131072
#define NOFF_UB1 163840
#define NOFF_UB2 164352
#define NODEF_SMEM_BYTES (164608)

// bf16 split of a float pair -> packed bf16x2 (low half = first arg / even idx)
static __device__ __forceinline__ void bsplit2(float x0, float x1,
                                               uint32_t& hi, uint32_t& lo) {
    uint32_t h;
    asm("cvt.rn.bf16x2.f32 %0, %1, %2;" : "=r"(h) : "f"(x1), "f"(x0));
    float r0 = x0 - __uint_as_float(h << 16);
    float r1 = x1 - __uint_as_float(h & 0xFFFF0000u);
    uint32_t l;
    asm("cvt.rn.bf16x2.f32 %0, %1, %2;" : "=r"(l) : "f"(r1), "f"(r0));
    hi = h; lo = l;
}

// D += A(16x16 bf16) * B(16x8 bf16), fp32 accum
static __device__ __forceinline__ void mma_bf16(float* d, const uint32_t* a,
                                                uint32_t b0, uint32_t b1) {
    asm volatile("mma.sync.aligned.m16n8k16.row.col.f32.bf16.bf16.f32 "
        "{%0,%1,%2,%3}, {%4,%5,%6,%7}, {%8,%9}, {%0,%1,%2,%3};"
        : "+f"(d[0]), "+f"(d[1]), "+f"(d[2]), "+f"(d[3])
        : "r"(a[0]), "r"(a[1]), "r"(a[2]), "r"(a[3]), "r"(b0), "r"(b1));
}
// 3-pass split MMA, single accumulator (node kernel — proven)
static __device__ __forceinline__ void mma3(float* C, const uint32_t* ah,
                                            const uint32_t* al, uint4 bw) {
    mma_bf16(C, ah, bw.x, bw.y);
    mma_bf16(C, ah, bw.z, bw.w);
    mma_bf16(C, al, bw.x, bw.y);
}
// 3-pass split MMA, TWO independent accumulators (breaks the serial chain):
//   Ch += Ah*Bh   (independent)
//   Cl += Ah*Bl; Cl += Al*Bh
static __device__ __forceinline__ void mma3s(float* Ch, float* Cl,
                                             const uint32_t* ah,
                                             const uint32_t* al, uint4 bw) {
    mma_bf16(Ch, ah, bw.x, bw.y);
    mma_bf16(Cl, ah, bw.z, bw.w);
    mma_bf16(Cl, al, bw.x, bw.y);
}

// Stage one weight B-fragment set (hi/lo interleaved uint4) from row-major W[k][n].
#define STAGE_FRAGS(dst_off, KC, NC, KROW_EXPR, SRC_PTR, SRC_N, STRIDE)         \
    for (int idx = tid; idx < (KC) * (NC) * 32; idx += (STRIDE)) {              \
        int T = idx & 31, nc = (idx >> 5) % (NC), kc = idx / ((NC) * 32);       \
        int n = nc * 8 + (T >> 2);                                              \
        int k0 = kc * 16 + (T & 3) * 2;                                         \
        int ka = (KROW_EXPR(k0)), kb = (KROW_EXPR(k0 + 1));                     \
        int kd = (KROW_EXPR(k0 + 8)), ke = (KROW_EXPR(k0 + 9));                 \
        float w00 = (SRC_PTR)[ka * (SRC_N) + n], w01 = (SRC_PTR)[kb * (SRC_N) + n]; \
        float w10 = (SRC_PTR)[kd * (SRC_N) + n], w11 = (SRC_PTR)[ke * (SRC_N) + n]; \
        uint32_t b0h, b0l, b1h, b1l;                                            \
        bsplit2(w00, w01, b0h, b0l);                                            \
        bsplit2(w10, w11, b1h, b1l);                                            \
        *(uint4*)(smem + (dst_off) + idx * 16) = make_uint4(b0h, b1h, b0l, b1l); \
    }

#define KR_ID(k)    (k)
#define KR_W1E(k)   (128 + (k))
#define KR_P(k)     ((k) < 64 ? (k) : (k) + 96)
#define KR_Q(k)     (64 + (k))

// ---------------------------------------------------------------------------
// Fused node kernel (unchanged from R9 — proven, ~48us)
// ---------------------------------------------------------------------------
__global__ __launch_bounds__(TPB_N, 1)
void node_fused_kernel(const float* __restrict__ nf,
                       const float* __restrict__ stx,
                       const float* __restrict__ mW1,
                       const float* __restrict__ uW1, const float* __restrict__ ub1,
                       const float* __restrict__ uW2, const float* __restrict__ ub2,
                       float* __restrict__ out_node,
                       float* __restrict__ agg)
{
    extern __shared__ char smem[];
    const int tid  = threadIdx.x;
    const int w    = tid >> 5;
    const int lane = tid & 31;
    const int m    = lane & 3;
    const int qrow = lane >> 2;

    STAGE_FRAGS(NOFF_BP,  6, 16, KR_P,  mW1, 128, TPB_N)
    STAGE_FRAGS(NOFF_BQ,  4, 16, KR_Q,  mW1, 128, TPB_N)
    STAGE_FRAGS(NOFF_BU1, 6, 16, KR_ID, uW1, 128, TPB_N)
    STAGE_FRAGS(NOFF_BU2, 8, 8,  KR_ID, uW2, 64,  TPB_N)
    float* ub1s = (float*)(smem + NOFF_UB1);
    float* ub2s = (float*)(smem + NOFF_UB2);
    if (tid < 128) ub1s[tid] = ub1[tid];
    if (tid < 64)  ub2s[tid] = ub2[tid];
    __syncthreads();

    const int gw = blockIdx.x * 8 + w;
    const int gstride = gridDim.x * 8;
    const float4 z4 = make_float4(0.f, 0.f, 0.f, 0.f);

    for (int wt = gw; wt < N_WT_NODE; wt += gstride) {
        const int n0 = wt * 16 + qrow;
        const int n1 = n0 + 8;

        #pragma unroll
        for (int s = lane; s < 256; s += 32) {
            int r = s >> 4, q = s & 15;
            *(float4*)(agg + (size_t)(wt * 16 + r) * 64 + q * 4) = z4;
        }

        uint32_t xh[6][4], xl[6][4];
        #pragma unroll
        for (int kc = 0; kc < 4; kc++) {
            float2 v0  = __ldg((const float2*)(nf + (size_t)n0 * 64 + kc * 16 + 2 * m));
            float2 v1  = __ldg((const float2*)(nf + (size_t)n1 * 64 + kc * 16 + 2 * m));
            float2 v0b = __ldg((const float2*)(nf + (size_t)n0 * 64 + kc * 16 + 8 + 2 * m));
            float2 v1b = __ldg((const float2*)(nf + (size_t)n1 * 64 + kc * 16 + 8 + 2 * m));
            bsplit2(v0.x,  v0.y,  xh[kc][0], xl[kc][0]);
            bsplit2(v1.x,  v1.y,  xh[kc][1], xl[kc][1]);
            bsplit2(v0b.x, v0b.y, xh[kc][2], xl[kc][2]);
            bsplit2(v1b.x, v1b.y, xh[kc][3], xl[kc][3]);
        }
        #pragma unroll
        for (int kc = 4; kc < 6; kc++) {
            int c = (kc - 4) * 16;
            float2 v0  = __ldg((const float2*)(stx + (size_t)n0 * 32 + c + 2 * m));
            float2 v1  = __ldg((const float2*)(stx + (size_t)n1 * 32 + c + 2 * m));
            float2 v0b = __ldg((const float2*)(stx + (size_t)n0 * 32 + c + 8 + 2 * m));
            float2 v1b = __ldg((const float2*)(stx + (size_t)n1 * 32 + c + 8 + 2 * m));
            bsplit2(v0.x,  v0.y,  xh[kc][0], xl[kc][0]);
            bsplit2(v1.x,  v1.y,  xh[kc][1], xl[kc][1]);
            bsplit2(v0b.x, v0b.y, xh[kc][2], xl[kc][2]);
            bsplit2(v1b.x, v1b.y, xh[kc][3], xl[kc][3]);
        }

        {   // P (K=96)
            #pragma unroll
            for (int np = 0; np < 8; np++) {
                float C0[4] = {0.f, 0.f, 0.f, 0.f};
                float C1[4] = {0.f, 0.f, 0.f, 0.f};
                #pragma unroll
                for (int kc = 0; kc < 6; kc++) {
                    uint4 b0 = *(const uint4*)(smem + NOFF_BP + (((kc * 16 + np) * 32) + lane) * 16);
                    uint4 b1 = *(const uint4*)(smem + NOFF_BP + (((kc * 16 + np + 8) * 32) + lane) * 16);
                    mma3(C0, xh[kc], xl[kc], b0);
                    mma3(C1, xh[kc], xl[kc], b1);
                }
                *(float2*)(g_P + (size_t)n0 * 128 + np * 8 + 2 * m) = make_float2(C0[0], C0[1]);
                *(float2*)(g_P + (size_t)n1 * 128 + np * 8 + 2 * m) = make_float2(C0[2], C0[3]);
                *(float2*)(g_P + (size_t)n0 * 128 + (np + 8) * 8 + 2 * m) = make_float2(C1[0], C1[1]);
                *(float2*)(g_P + (size_t)n1 * 128 + (np + 8) * 8 + 2 * m) = make_float2(C1[2], C1[3]);
            }
        }
        {   // Q (K=64)
            #pragma unroll
            for (int np = 0; np < 8; np++) {
                float C0[4] = {0.f, 0.f, 0.f, 0.f};
                float C1[4] = {0.f, 0.f, 0.f, 0.f};
                #pragma unroll
                for (int kc = 0; kc < 4; kc++) {
                    uint4 b0 = *(const uint4*)(smem + NOFF_BQ + (((kc * 16 + np) * 32) + lane) * 16);
                    uint4 b1 = *(const uint4*)(smem + NOFF_BQ + (((kc * 16 + np + 8) * 32) + lane) * 16);
                    mma3(C0, xh[kc], xl[kc], b0);
                    mma3(C1, xh[kc], xl[kc], b1);
                }
                *(float2*)(g_Q + (size_t)n0 * 128 + np * 8 + 2 * m) = make_float2(C0[0], C0[1]);
                *(float2*)(g_Q + (size_t)n1 * 128 + np * 8 + 2 * m) = make_float2(C0[2], C0[3]);
                *(float2*)(g_Q + (size_t)n0 * 128 + (np + 8) * 8 + 2 * m) = make_float2(C1[0], C1[1]);
                *(float2*)(g_Q + (size_t)n1 * 128 + (np + 8) * 8 + 2 * m) = make_float2(C1[2], C1[3]);
            }
        }
        uint32_t A2h[8][4], A2l[8][4];
        {   // h = relu(x@uW1 + ub1)
            #pragma unroll
            for (int j = 0; j < 8; j++) {
                float2 ba = *(const float2*)(ub1s + (2 * j) * 8 + 2 * m);
                float2 bb = *(const float2*)(ub1s + (2 * j + 1) * 8 + 2 * m);
                float Ca[4] = {ba.x, ba.y, ba.x, ba.y};
                float Cb[4] = {bb.x, bb.y, bb.x, bb.y};
                #pragma unroll
                for (int kc = 0; kc < 6; kc++) {
                    uint4 ba4 = *(const uint4*)(smem + NOFF_BU1 + (((kc * 16 + 2 * j) * 32) + lane) * 16);
                    uint4 bb4 = *(const uint4*)(smem + NOFF_BU1 + (((kc * 16 + 2 * j + 1) * 32) + lane) * 16);
                    mma3(Ca, xh[kc], xl[kc], ba4);
                    mma3(Cb, xh[kc], xl[kc], bb4);
                }
                bsplit2(fmaxf(Ca[0], 0.f), fmaxf(Ca[1], 0.f), A2h[j][0], A2l[j][0]);
                bsplit2(fmaxf(Ca[2], 0.f), fmaxf(Ca[3], 0.f), A2h[j][1], A2l[j][1]);
                bsplit2(fmaxf(Cb[0], 0.f), fmaxf(Cb[1], 0.f), A2h[j][2], A2l[j][2]);
                bsplit2(fmaxf(Cb[2], 0.f), fmaxf(Cb[3], 0.f), A2h[j][3], A2l[j][3]);
            }
        }
        {   // out = nf + h@uW2 + ub2
            #pragma unroll
            for (int np = 0; np < 4; np++) {
                float2 b0v = *(const float2*)(ub2s + np * 8 + 2 * m);
                float2 b1v = *(const float2*)(ub2s + (np + 4) * 8 + 2 * m);
                float C0[4] = {b0v.x, b0v.y, b0v.x, b0v.y};
                float C1[4] = {b1v.x, b1v.y, b1v.x, b1v.y};
                #pragma unroll
                for (int kc = 0; kc < 8; kc++) {
                    uint4 b0 = *(const uint4*)(smem + NOFF_BU2 + (((kc * 8 + np) * 32) + lane) * 16);
                    uint4 b1 = *(const uint4*)(smem + NOFF_BU2 + (((kc * 8 + np + 4) * 32) + lane) * 16);
                    mma3(C0, A2h[kc], A2l[kc], b0);
                    mma3(C1, A2h[kc], A2l[kc], b1);
                }
                float2 r00 = __ldg((const float2*)(nf + (size_t)n0 * 64 + np * 8 + 2 * m));
                float2 r10 = __ldg((const float2*)(nf + (size_t)n1 * 64 + np * 8 + 2 * m));
                float2 r01 = __ldg((const float2*)(nf + (size_t)n0 * 64 + (np + 4) * 8 + 2 * m));
                float2 r11 = __ldg((const float2*)(nf + (size_t)n1 * 64 + (np + 4) * 8 + 2 * m));
                *(float2*)(out_node + (size_t)n0 * 64 + np * 8 + 2 * m) =
                    make_float2(r00.x + C0[0], r00.y + C0[1]);
                *(float2*)(out_node + (size_t)n1 * 64 + np * 8 + 2 * m) =
                    make_float2(r10.x + C0[2], r10.y + C0[3]);
                *(float2*)(out_node + (size_t)n0 * 64 + (np + 4) * 8 + 2 * m) =
                    make_float2(r01.x + C1[0], r01.y + C1[1]);
                *(float2*)(out_node + (size_t)n1 * 64 + (np + 4) * 8 + 2 * m) =
                    make_float2(r11.x + C1[2], r11.y + C1[3]);
            }
        }
    }
}

// ---------------------------------------------------------------------------
// Edge kernel: 10 warps, 4 nc-chains x split (Ch/Cl) accumulators per thread.
// ---------------------------------------------------------------------------
__global__ __launch_bounds__(TPB_E, 1)
void edge_mlp_kernel(const float* __restrict__ ef,
                     const float* __restrict__ mW1, const float* __restrict__ mb1,
                     const float* __restrict__ mW2, const float* __restrict__ mb2,
                     const float* __restrict__ mW3, const float* __restrict__ mb3,
                     const int*   __restrict__ eidx,
                     float* __restrict__ agg)
{
    extern __shared__ char smem[];
    const int tid  = threadIdx.x;
    const int w    = tid >> 5;
    const int lane = tid & 31;
    const int m    = lane & 3;
    const int qrow = lane >> 2;

    STAGE_FRAGS(OFF_W1, 2, 16, KR_W1E, mW1, 128, TPB_E)
    STAGE_FRAGS(OFF_W2, 8, 16, KR_ID,  mW2, 128, TPB_E)
    STAGE_FRAGS(OFF_W3, 8, 8,  KR_ID,  mW3, 64,  TPB_E)
    float* b1s = (float*)(smem + OFF_B1);
    float* b2s = (float*)(smem + OFF_B2);
    float* b3s = (float*)(smem + OFF_B3);
    if (tid < 128) { b1s[tid] = mb1[tid]; b2s[tid] = mb2[tid]; }
    if (tid < 64)  { b3s[tid] = mb3[tid]; }
    __syncthreads();

    float* pq = (float*)(smem + OFF_PQ + w * PQ_WARP_BYTES);   // [16][PQ_STRIDE]
    const float4 bv1 = ((const float4*)b1s)[lane];

    const int gw = blockIdx.x * NW_E + w;
    const int gstride = gridDim.x * NW_E;

    for (int wt = gw; wt < N_WT_EDGE; wt += gstride) {
        const int base_e = wt * 16;

        int2 se = make_int2(0, 0);
        if (lane < 16) se = ((const int2*)eidx)[base_e + lane];
        __syncwarp();    // also fences pq/msg reuse from previous tile

        // ---- prefetch ef (K=32) ----
        const float* e0p = ef + (size_t)(base_e + qrow) * 32;
        const float* e1p = ef + (size_t)(base_e + qrow + 8) * 32;
        float2 v00 = __ldg((const float2*)(e0p + 2 * m));
        float2 v01 = __ldg((const float2*)(e0p + 2 * m + 8));
        float2 v02 = __ldg((const float2*)(e0p + 2 * m + 16));
        float2 v03 = __ldg((const float2*)(e0p + 2 * m + 24));
        float2 v10 = __ldg((const float2*)(e1p + 2 * m));
        float2 v11 = __ldg((const float2*)(e1p + 2 * m + 8));
        float2 v12 = __ldg((const float2*)(e1p + 2 * m + 16));
        float2 v13 = __ldg((const float2*)(e1p + 2 * m + 24));

        // ---- stage PQ = P[src] + Q[dst] + b1 into warp-private smem ----
        #pragma unroll 4
        for (int r = 0; r < 16; r++) {
            int sr = __shfl_sync(0xffffffffu, se.x, r);
            int dr = __shfl_sync(0xffffffffu, se.y, r);
            float4 pv = __ldg((const float4*)g_P + (size_t)sr * 32 + lane);
            float4 qv = __ldg((const float4*)g_Q + (size_t)dr * 32 + lane);
            float4 o;
            o.x = pv.x + qv.x + bv1.x; o.y = pv.y + qv.y + bv1.y;
            o.z = pv.z + qv.z + bv1.z; o.w = pv.w + qv.w + bv1.w;
            *(float4*)(pq + r * PQ_STRIDE + lane * 4) = o;
        }
        __syncwarp();

        // ---- A1 fragments ----
        uint32_t A1h[2][4], A1l[2][4];
        bsplit2(v00.x, v00.y, A1h[0][0], A1l[0][0]);
        bsplit2(v10.x, v10.y, A1h[0][1], A1l[0][1]);
        bsplit2(v01.x, v01.y, A1h[0][2], A1l[0][2]);
        bsplit2(v11.x, v11.y, A1h[0][3], A1l[0][3]);
        bsplit2(v02.x, v02.y, A1h[1][0], A1l[1][0]);
        bsplit2(v12.x, v12.y, A1h[1][1], A1l[1][1]);
        bsplit2(v03.x, v03.y, A1h[1][2], A1l[1][2]);
        bsplit2(v13.x, v13.y, A1h[1][3], A1l[1][3]);

        // ---- L1 (4 nc-chains, split acc): Ch init = PQ, Cl = 0 ----
        uint32_t A2h[8][4], A2l[8][4];
        #pragma unroll
        for (int j = 0; j < 4; j++) {
            int j2 = j + 4;
            float Ch[4][4], Cl[4][4];
            {
                float2 pa0 = *(const float2*)(pq + qrow * PQ_STRIDE + 16 * j + 2 * m);
                float2 pa1 = *(const float2*)(pq + (qrow + 8) * PQ_STRIDE + 16 * j + 2 * m);
                float2 pb0 = *(const float2*)(pq + qrow * PQ_STRIDE + 16 * j + 8 + 2 * m);
                float2 pb1 = *(const float2*)(pq + (qrow + 8) * PQ_STRIDE + 16 * j + 8 + 2 * m);
                float2 qa0 = *(const float2*)(pq + qrow * PQ_STRIDE + 16 * j2 + 2 * m);
                float2 qa1 = *(const float2*)(pq + (qrow + 8) * PQ_STRIDE + 16 * j2 + 2 * m);
                float2 qb0 = *(const float2*)(pq + qrow * PQ_STRIDE + 16 * j2 + 8 + 2 * m);
                float2 qb1 = *(const float2*)(pq + (qrow + 8) * PQ_STRIDE + 16 * j2 + 8 + 2 * m);
                Ch[0][0] = pa0.x; Ch[0][1] = pa0.y; Ch[0][2] = pa1.x; Ch[0][3] = pa1.y;
                Ch[1][0] = pb0.x; Ch[1][1] = pb0.y; Ch[1][2] = pb1.x; Ch[1][3] = pb1.y;
                Ch[2][0] = qa0.x; Ch[2][1] = qa0.y; Ch[2][2] = qa1.x; Ch[2][3] = qa1.y;
                Ch[3][0] = qb0.x; Ch[3][1] = qb0.y; Ch[3][2] = qb1.x; Ch[3][3] = qb1.y;
                #pragma unroll
                for (int c = 0; c < 4; c++)
                    #pragma unroll
                    for (int i = 0; i < 4; i++) Cl[c][i] = 0.f;
            }
            #pragma unroll
            for (int kc = 0; kc < 2; kc++) {
                uint4 b0 = *(const uint4*)(smem + OFF_W1 + (((kc * 16 + 2 * j) * 32) + lane) * 16);
                uint4 b1 = *(const uint4*)(smem + OFF_W1 + (((kc * 16 + 2 * j + 1) * 32) + lane) * 16);
                uint4 b2 = *(const uint4*)(smem + OFF_W1 + (((kc * 16 + 2 * j2) * 32) + lane) * 16);
                uint4 b3 = *(const uint4*)(smem + OFF_W1 + (((kc * 16 + 2 * j2 + 1) * 32) + lane) * 16);
                mma3s(Ch[0], Cl[0], A1h[kc], A1l[kc], b0);
                mma3s(Ch[1], Cl[1], A1h[kc], A1l[kc], b1);
                mma3s(Ch[2], Cl[2], A1h[kc], A1l[kc], b2);
                mma3s(Ch[3], Cl[3], A1h[kc], A1l[kc], b3);
            }
            bsplit2(fmaxf(Ch[0][0] + Cl[0][0], 0.f), fmaxf(Ch[0][1] + Cl[0][1], 0.f), A2h[j][0], A2l[j][0]);
            bsplit2(fmaxf(Ch[0][2] + Cl[0][2], 0.f), fmaxf(Ch[0][3] + Cl[0][3], 0.f), A2h[j][1], A2l[j][1]);
            bsplit2(fmaxf(Ch[1][0] + Cl[1][0], 0.f), fmaxf(Ch[1][1] + Cl[1][1], 0.f), A2h[j][2], A2l[j][2]);
            bsplit2(fmaxf(Ch[1][2] + Cl[1][2], 0.f), fmaxf(Ch[1][3] + Cl[1][3], 0.f), A2h[j][3], A2l[j][3]);
            bsplit2(fmaxf(Ch[2][0] + Cl[2][0], 0.f), fmaxf(Ch[2][1] + Cl[2][1], 0.f), A2h[j2][0], A2l[j2][0]);
            bsplit2(fmaxf(Ch[2][2] + Cl[2][2], 0.f), fmaxf(Ch[2][3] + Cl[2][3], 0.f), A2h[j2][1], A2l[j2][1]);
            bsplit2(fmaxf(Ch[3][0] + Cl[3][0], 0.f), fmaxf(Ch[3][1] + Cl[3][1], 0.f), A2h[j2][2], A2l[j2][2]);
            bsplit2(fmaxf(Ch[3][2] + Cl[3][2], 0.f), fmaxf(Ch[3][3] + Cl[3][3], 0.f), A2h[j2][3], A2l[j2][3]);
        }

        // ---- L2 (4 nc-chains, split acc): Ch init = b2, Cl = 0 ----
        uint32_t A3h[8][4], A3l[8][4];
        #pragma unroll
        for (int j = 0; j < 4; j++) {
            int j2 = j + 4;
            float Ch[4][4], Cl[4][4];
            {
                float2 ba2 = *(const float2*)(b2s + (2 * j) * 8 + 2 * m);
                float2 bb2 = *(const float2*)(b2s + (2 * j + 1) * 8 + 2 * m);
                float2 bc2 = *(const float2*)(b2s + (2 * j2) * 8 + 2 * m);
                float2 bd2 = *(const float2*)(b2s + (2 * j2 + 1) * 8 + 2 * m);
                Ch[0][0] = ba2.x; Ch[0][1] = ba2.y; Ch[0][2] = ba2.x; Ch[0][3] = ba2.y;
                Ch[1][0] = bb2.x; Ch[1][1] = bb2.y; Ch[1][2] = bb2.x; Ch[1][3] = bb2.y;
                Ch[2][0] = bc2.x; Ch[2][1] = bc2.y; Ch[2][2] = bc2.x; Ch[2][3] = bc2.y;
                Ch[3][0] = bd2.x; Ch[3][1] = bd2.y; Ch[3][2] = bd2.x; Ch[3][3] = bd2.y;
                #pragma unroll
                for (int c = 0; c < 4; c++)
                    #pragma unroll
                    for (int i = 0; i < 4; i++) Cl[c][i] = 0.f;
            }
            #pragma unroll
            for (int kc = 0; kc < 8; kc++) {
                uint4 b0 = *(const uint4*)(smem + OFF_W2 + (((kc * 16 + 2 * j) * 32) + lane) * 16);
                uint4 b1 = *(const uint4*)(smem + OFF_W2 + (((kc * 16 + 2 * j + 1) * 32) + lane) * 16);
                uint4 b2 = *(const uint4*)(smem + OFF_W2 + (((kc * 16 + 2 * j2) * 32) + lane) * 16);
                uint4 b3 = *(const uint4*)(smem + OFF_W2 + (((kc * 16 + 2 * j2 + 1) * 32) + lane) * 16);
                mma3s(Ch[0], Cl[0], A2h[kc], A2l[kc], b0);
                mma3s(Ch[1], Cl[1], A2h[kc], A2l[kc], b1);
                mma3s(Ch[2], Cl[2], A2h[kc], A2l[kc], b2);
                mma3s(Ch[3], Cl[3], A2h[kc], A2l[kc], b3);
            }
            bsplit2(fmaxf(Ch[0][0] + Cl[0][0], 0.f), fmaxf(Ch[0][1] + Cl[0][1], 0.f), A3h[j][0], A3l[j][0]);
            bsplit2(fmaxf(Ch[0][2] + Cl[0][2], 0.f), fmaxf(Ch[0][3] + Cl[0][3], 0.f), A3h[j][1], A3l[j][1]);
            bsplit2(fmaxf(Ch[1][0] + Cl[1][0], 0.f), fmaxf(Ch[1][1] + Cl[1][1], 0.f), A3h[j][2], A3l[j][2]);
            bsplit2(fmaxf(Ch[1][2] + Cl[1][2], 0.f), fmaxf(Ch[1][3] + Cl[1][3], 0.f), A3h[j][3], A3l[j][3]);
            bsplit2(fmaxf(Ch[2][0] + Cl[2][0], 0.f), fmaxf(Ch[2][1] + Cl[2][1], 0.f), A3h[j2][0], A3l[j2][0]);
            bsplit2(fmaxf(Ch[2][2] + Cl[2][2], 0.f), fmaxf(Ch[2][3] + Cl[2][3], 0.f), A3h[j2][1], A3l[j2][1]);
            bsplit2(fmaxf(Ch[3][0] + Cl[3][0], 0.f), fmaxf(Ch[3][1] + Cl[3][1], 0.f), A3h[j2][2], A3l[j2][2]);
            bsplit2(fmaxf(Ch[3][2] + Cl[3][2], 0.f), fmaxf(Ch[3][3] + Cl[3][3], 0.f), A3h[j2][3], A3l[j2][3]);
        }

        // ---- L3 (4 nc-chains, split acc): Ch init = b3; -> msg ----
        float* msg = pq;
        __syncwarp();   // pq reads (L1 init) complete before msg overwrite
        #pragma unroll
        for (int nc = 0; nc < 2; nc++) {
            float Ch[4][4], Cl[4][4];
            {
                float2 b0v = *(const float2*)(b3s + nc * 8 + 2 * m);
                float2 b1v = *(const float2*)(b3s + (nc + 2) * 8 + 2 * m);
                float2 b2v = *(const float2*)(b3s + (nc + 4) * 8 + 2 * m);
                float2 b3v = *(const float2*)(b3s + (nc + 6) * 8 + 2 * m);
                Ch[0][0] = b0v.x; Ch[0][1] = b0v.y; Ch[0][2] = b0v.x; Ch[0][3] = b0v.y;
                Ch[1][0] = b1v.x; Ch[1][1] = b1v.y; Ch[1][2] = b1v.x; Ch[1][3] = b1v.y;
                Ch[2][0] = b2v.x; Ch[2][1] = b2v.y; Ch[2][2] = b2v.x; Ch[2][3] = b2v.y;
                Ch[3][0] = b3v.x; Ch[3][1] = b3v.y; Ch[3][2] = b3v.x; Ch[3][3] = b3v.y;
                #pragma unroll
                for (int c = 0; c < 4; c++)
                    #pragma unroll
                    for (int i = 0; i < 4; i++) Cl[c][i] = 0.f;
            }
            #pragma unroll
            for (int kc = 0; kc < 8; kc++) {
                uint4 b0 = *(const uint4*)(smem + OFF_W3 + (((kc * 8 + nc) * 32) + lane) * 16);
                uint4 b1 = *(const uint4*)(smem + OFF_W3 + (((kc * 8 + nc + 2) * 32) + lane) * 16);
                uint4 b2 = *(const uint4*)(smem + OFF_W3 + (((kc * 8 + nc + 4) * 32) + lane) * 16);
                uint4 b3 = *(const uint4*)(smem + OFF_W3 + (((kc * 8 + nc + 6) * 32) + lane) * 16);
                mma3s(Ch[0], Cl[0], A3h[kc], A3l[kc], b0);
                mma3s(Ch[1], Cl[1], A3h[kc], A3l[kc], b1);
                mma3s(Ch[2], Cl[2], A3h[kc], A3l[kc], b2);
                mma3s(Ch[3], Cl[3], A3h[kc], A3l[kc], b3);
            }
            #pragma unroll
            for (int c = 0; c < 4; c++) {
                int n8 = 8 * (nc + 2 * c);
                *(float2*)(msg + qrow * 72 + n8 + 2 * m) =
                    make_float2(Ch[c][0] + Cl[c][0], Ch[c][1] + Cl[c][1]);
                *(float2*)(msg + (qrow + 8) * 72 + n8 + 2 * m) =
                    make_float2(Ch[c][2] + Cl[c][2], Ch[c][3] + Cl[c][3]);
            }
        }
        __syncwarp();

        // ---- scatter: 16 edges x 16 float4 atomics ----
        #pragma unroll
        for (int it = 0; it < 8; it++) {
            int slot = it * 32 + lane;
            int e = slot >> 4, q = slot & 15;
            float4 v = *(const float4*)(msg + e * 72 + q * 4);
            int dn = __shfl_sync(0xffffffffu, se.y, e);
            atomicAdd(((float4*)(agg + (size_t)dn * 64)) + q, v);
        }
    }
}

extern "C" void kernel_launch(void* const* d_in, const int* in_sizes, int n_in,
                              void* d_out, int out_size)
{
    const float* nf  = (const float*)d_in[0];
    const float* ef  = (const float*)d_in[1];
    const float* stx = (const float*)d_in[2];
    const float* mW1 = (const float*)d_in[3];
    const float* mb1 = (const float*)d_in[4];
    const float* mW2 = (const float*)d_in[5];
    const float* mb2 = (const float*)d_in[6];
    const float* mW3 = (const float*)d_in[7];
    const float* mb3 = (const float*)d_in[8];
    const float* uW1 = (const float*)d_in[9];
    const float* ub1 = (const float*)d_in[10];
    const float* uW2 = (const float*)d_in[11];
    const float* ub2 = (const float*)d_in[12];
    const int*  eidx = (const int*)d_in[13];

    float* out_node = (float*)d_out;
    float* agg      = out_node + (size_t)N_NODES_C * 64;

    cudaFuncSetAttribute(edge_mlp_kernel,
                         cudaFuncAttributeMaxDynamicSharedMemorySize, EDGE_SMEM_BYTES);
    cudaFuncSetAttribute(node_fused_kernel,
                         cudaFuncAttributeMaxDynamicSharedMemorySize, NODEF_SMEM_BYTES);

    int dev = 0;
    cudaGetDevice(&dev);
    int sms = 148;
    cudaDeviceGetAttribute(&sms, cudaDevAttrMultiProcessorCount, dev);

    node_fused_kernel<<<sms, TPB_N, NODEF_SMEM_BYTES>>>(nf, stx, mW1, uW1, ub1, uW2, ub2,
                                                        out_node, agg);
    edge_mlp_kernel<<<sms, TPB_E, EDGE_SMEM_BYTES>>>(ef, mW1, mb1, mW2, mb2,
                                                     mW3, mb3, eidx, agg);
}

// round 11
// speedup vs baseline: 1.2468x; 1.2468x over previous
#include <cuda_runtime.h>
#include <cuda_fp16.h>
#include <cstdint>

#define N_NODES_C 50000
#define N_EDGES_C 800000

#define TPB_N 256          // node kernel: 8 warps
#define TPB_E 384          // edge kernel: 12 warps
#define NW_E 12
#define N_WT_EDGE (N_EDGES_C / 16)          // 50000 warp-tiles
#define N_WT_NODE (N_NODES_C / 16)          // 3125 warp-tiles

// Per-node layer-1 partials (scratch; no allocation allowed)
__device__ float g_P[(size_t)N_NODES_C * 128];   // nf@W1[0:64] + st@W1[160:192]
__device__ float g_Q[(size_t)N_NODES_C * 128];   // nf@W1[64:128]

// ---------------- edge kernel SMEM (bytes) ----------------
#define OFF_W1 0                          // kc=2, nc=16 : 16384
#define OFF_W2 16384                      // kc=8, nc=16 : 65536
#define OFF_W3 81920                      // kc=8, nc=8  : 32768
#define OFF_B1 114688                     // 128 f32
#define OFF_B2 115200                     // 128 f32
#define OFF_B3 115712                     // 64 f32
#define OFF_PQ 115968                     // 12 warps * 16 rows * 132 f32
#define PQ_STRIDE 132
#define PQ_WARP_BYTES (16*PQ_STRIDE*4)    // 8448
#define EDGE_SMEM_BYTES (OFF_PQ + NW_E*PQ_WARP_BYTES)   // 217344

// ---------------- fused node kernel SMEM (bytes) ----------------
#define NOFF_BP  0
#define NOFF_BQ  49152
#define NOFF_BU1 81920
#define NOFF_BU2 131072
#define NOFF_UB1 163840
#define NOFF_UB2 164352
#define NODEF_SMEM_BYTES (164608)

// pack two floats into fp16x2 (low half = first arg)
static __device__ __forceinline__ uint32_t hpack2(float x0, float x1) {
    uint32_t r;
    asm("cvt.rn.f16x2.f32 %0, %1, %2;" : "=r"(r) : "f"(x1), "f"(x0));
    return r;
}
// fp16 split of a float pair -> hi fp16x2 + residual-lo fp16x2 (22-bit exact)
static __device__ __forceinline__ void hsplit2(float x0, float x1,
                                               uint32_t& hi, uint32_t& lo) {
    uint32_t h = hpack2(x0, x1);
    __half2 hh = *reinterpret_cast<__half2*>(&h);
    float r0 = x0 - __half2float(__low2half(hh));
    float r1 = x1 - __half2float(__high2half(hh));
    lo = hpack2(r0, r1);
    hi = h;
}

// D += A(16x16 fp16) * B(16x8 fp16), fp32 accum
static __device__ __forceinline__ void mma_f16(float* d, const uint32_t* a,
                                               uint32_t b0, uint32_t b1) {
    asm volatile("mma.sync.aligned.m16n8k16.row.col.f32.f16.f16.f32 "
        "{%0,%1,%2,%3}, {%4,%5,%6,%7}, {%8,%9}, {%0,%1,%2,%3};"
        : "+f"(d[0]), "+f"(d[1]), "+f"(d[2]), "+f"(d[3])
        : "r"(a[0]), "r"(a[1]), "r"(a[2]), "r"(a[3]), "r"(b0), "r"(b1));
}
// 2-pass weight-split MMA, independent accumulators:
//   Ch += A*Bh ; Cl += A*Bl      (bw = {b0h,b1h,b0l,b1l})
static __device__ __forceinline__ void mma2s(float* Ch, float* Cl,
                                             const uint32_t* a, uint4 bw) {
    mma_f16(Ch, a, bw.x, bw.y);
    mma_f16(Cl, a, bw.z, bw.w);
}

// Stage one weight B-fragment set (fp16 hi/lo interleaved uint4) from W[k][n].
#define STAGE_FRAGS(dst_off, KC, NC, KROW_EXPR, SRC_PTR, SRC_N, STRIDE)         \
    for (int idx = tid; idx < (KC) * (NC) * 32; idx += (STRIDE)) {              \
        int T = idx & 31, nc = (idx >> 5) % (NC), kc = idx / ((NC) * 32);       \
        int n = nc * 8 + (T >> 2);                                              \
        int k0 = kc * 16 + (T & 3) * 2;                                         \
        int ka = (KROW_EXPR(k0)), kb = (KROW_EXPR(k0 + 1));                     \
        int kd = (KROW_EXPR(k0 + 8)), ke = (KROW_EXPR(k0 + 9));                 \
        float w00 = (SRC_PTR)[ka * (SRC_N) + n], w01 = (SRC_PTR)[kb * (SRC_N) + n]; \
        float w10 = (SRC_PTR)[kd * (SRC_N) + n], w11 = (SRC_PTR)[ke * (SRC_N) + n]; \
        uint32_t b0h, b0l, b1h, b1l;                                            \
        hsplit2(w00, w01, b0h, b0l);                                            \
        hsplit2(w10, w11, b1h, b1l);                                            \
        *(uint4*)(smem + (dst_off) + idx * 16) = make_uint4(b0h, b1h, b0l, b1l); \
    }

#define KR_ID(k)    (k)
#define KR_W1E(k)   (128 + (k))
#define KR_P(k)     ((k) < 64 ? (k) : (k) + 96)
#define KR_Q(k)     (64 + (k))

// ---------------------------------------------------------------------------
// Fused node kernel: fp16 activations, fp16-split weights (2-pass)
// ---------------------------------------------------------------------------
__global__ __launch_bounds__(TPB_N, 1)
void node_fused_kernel(const float* __restrict__ nf,
                       const float* __restrict__ stx,
                       const float* __restrict__ mW1,
                       const float* __restrict__ uW1, const float* __restrict__ ub1,
                       const float* __restrict__ uW2, const float* __restrict__ ub2,
                       float* __restrict__ out_node,
                       float* __restrict__ agg)
{
    extern __shared__ char smem[];
    const int tid  = threadIdx.x;
    const int w    = tid >> 5;
    const int lane = tid & 31;
    const int m    = lane & 3;
    const int qrow = lane >> 2;

    STAGE_FRAGS(NOFF_BP,  6, 16, KR_P,  mW1, 128, TPB_N)
    STAGE_FRAGS(NOFF_BQ,  4, 16, KR_Q,  mW1, 128, TPB_N)
    STAGE_FRAGS(NOFF_BU1, 6, 16, KR_ID, uW1, 128, TPB_N)
    STAGE_FRAGS(NOFF_BU2, 8, 8,  KR_ID, uW2, 64,  TPB_N)
    float* ub1s = (float*)(smem + NOFF_UB1);
    float* ub2s = (float*)(smem + NOFF_UB2);
    if (tid < 128) ub1s[tid] = ub1[tid];
    if (tid < 64)  ub2s[tid] = ub2[tid];
    __syncthreads();

    const int gw = blockIdx.x * 8 + w;
    const int gstride = gridDim.x * 8;
    const float4 z4 = make_float4(0.f, 0.f, 0.f, 0.f);

    for (int wt = gw; wt < N_WT_NODE; wt += gstride) {
        const int n0 = wt * 16 + qrow;
        const int n1 = n0 + 8;

        #pragma unroll
        for (int s = lane; s < 256; s += 32) {
            int r = s >> 4, q = s & 15;
            *(float4*)(agg + (size_t)(wt * 16 + r) * 64 + q * 4) = z4;
        }

        // ---- A fragments (single fp16): x = [nf(64) | st(32)] ----
        uint32_t xA[6][4];
        #pragma unroll
        for (int kc = 0; kc < 4; kc++) {
            float2 v0  = __ldg((const float2*)(nf + (size_t)n0 * 64 + kc * 16 + 2 * m));
            float2 v1  = __ldg((const float2*)(nf + (size_t)n1 * 64 + kc * 16 + 2 * m));
            float2 v0b = __ldg((const float2*)(nf + (size_t)n0 * 64 + kc * 16 + 8 + 2 * m));
            float2 v1b = __ldg((const float2*)(nf + (size_t)n1 * 64 + kc * 16 + 8 + 2 * m));
            xA[kc][0] = hpack2(v0.x, v0.y);
            xA[kc][1] = hpack2(v1.x, v1.y);
            xA[kc][2] = hpack2(v0b.x, v0b.y);
            xA[kc][3] = hpack2(v1b.x, v1b.y);
        }
        #pragma unroll
        for (int kc = 4; kc < 6; kc++) {
            int c = (kc - 4) * 16;
            float2 v0  = __ldg((const float2*)(stx + (size_t)n0 * 32 + c + 2 * m));
            float2 v1  = __ldg((const float2*)(stx + (size_t)n1 * 32 + c + 2 * m));
            float2 v0b = __ldg((const float2*)(stx + (size_t)n0 * 32 + c + 8 + 2 * m));
            float2 v1b = __ldg((const float2*)(stx + (size_t)n1 * 32 + c + 8 + 2 * m));
            xA[kc][0] = hpack2(v0.x, v0.y);
            xA[kc][1] = hpack2(v1.x, v1.y);
            xA[kc][2] = hpack2(v0b.x, v0b.y);
            xA[kc][3] = hpack2(v1b.x, v1b.y);
        }

        {   // P (K=96)
            #pragma unroll
            for (int np = 0; np < 8; np++) {
                float C0h[4] = {0,0,0,0}, C0l[4] = {0,0,0,0};
                float C1h[4] = {0,0,0,0}, C1l[4] = {0,0,0,0};
                #pragma unroll
                for (int kc = 0; kc < 6; kc++) {
                    uint4 b0 = *(const uint4*)(smem + NOFF_BP + (((kc * 16 + np) * 32) + lane) * 16);
                    uint4 b1 = *(const uint4*)(smem + NOFF_BP + (((kc * 16 + np + 8) * 32) + lane) * 16);
                    mma2s(C0h, C0l, xA[kc], b0);
                    mma2s(C1h, C1l, xA[kc], b1);
                }
                *(float2*)(g_P + (size_t)n0 * 128 + np * 8 + 2 * m) =
                    make_float2(C0h[0] + C0l[0], C0h[1] + C0l[1]);
                *(float2*)(g_P + (size_t)n1 * 128 + np * 8 + 2 * m) =
                    make_float2(C0h[2] + C0l[2], C0h[3] + C0l[3]);
                *(float2*)(g_P + (size_t)n0 * 128 + (np + 8) * 8 + 2 * m) =
                    make_float2(C1h[0] + C1l[0], C1h[1] + C1l[1]);
                *(float2*)(g_P + (size_t)n1 * 128 + (np + 8) * 8 + 2 * m) =
                    make_float2(C1h[2] + C1l[2], C1h[3] + C1l[3]);
            }
        }
        {   // Q (K=64)
            #pragma unroll
            for (int np = 0; np < 8; np++) {
                float C0h[4] = {0,0,0,0}, C0l[4] = {0,0,0,0};
                float C1h[4] = {0,0,0,0}, C1l[4] = {0,0,0,0};
                #pragma unroll
                for (int kc = 0; kc < 4; kc++) {
                    uint4 b0 = *(const uint4*)(smem + NOFF_BQ + (((kc * 16 + np) * 32) + lane) * 16);
                    uint4 b1 = *(const uint4*)(smem + NOFF_BQ + (((kc * 16 + np + 8) * 32) + lane) * 16);
                    mma2s(C0h, C0l, xA[kc], b0);
                    mma2s(C1h, C1l, xA[kc], b1);
                }
                *(float2*)(g_Q + (size_t)n0 * 128 + np * 8 + 2 * m) =
                    make_float2(C0h[0] + C0l[0], C0h[1] + C0l[1]);
                *(float2*)(g_Q + (size_t)n1 * 128 + np * 8 + 2 * m) =
                    make_float2(C0h[2] + C0l[2], C0h[3] + C0l[3]);
                *(float2*)(g_Q + (size_t)n0 * 128 + (np + 8) * 8 + 2 * m) =
                    make_float2(C1h[0] + C1l[0], C1h[1] + C1l[1]);
                *(float2*)(g_Q + (size_t)n1 * 128 + (np + 8) * 8 + 2 * m) =
                    make_float2(C1h[2] + C1l[2], C1h[3] + C1l[3]);
            }
        }
        uint32_t A2[8][4];
        {   // h = relu(x@uW1 + ub1)
            #pragma unroll
            for (int j = 0; j < 8; j++) {
                float2 ba = *(const float2*)(ub1s + (2 * j) * 8 + 2 * m);
                float2 bb = *(const float2*)(ub1s + (2 * j + 1) * 8 + 2 * m);
                float Cah[4] = {ba.x, ba.y, ba.x, ba.y}, Cal[4] = {0,0,0,0};
                float Cbh[4] = {bb.x, bb.y, bb.x, bb.y}, Cbl[4] = {0,0,0,0};
                #pragma unroll
                for (int kc = 0; kc < 6; kc++) {
                    uint4 ba4 = *(const uint4*)(smem + NOFF_BU1 + (((kc * 16 + 2 * j) * 32) + lane) * 16);
                    uint4 bb4 = *(const uint4*)(smem + NOFF_BU1 + (((kc * 16 + 2 * j + 1) * 32) + lane) * 16);
                    mma2s(Cah, Cal, xA[kc], ba4);
                    mma2s(Cbh, Cbl, xA[kc], bb4);
                }
                A2[j][0] = hpack2(fmaxf(Cah[0] + Cal[0], 0.f), fmaxf(Cah[1] + Cal[1], 0.f));
                A2[j][1] = hpack2(fmaxf(Cah[2] + Cal[2], 0.f), fmaxf(Cah[3] + Cal[3], 0.f));
                A2[j][2] = hpack2(fmaxf(Cbh[0] + Cbl[0], 0.f), fmaxf(Cbh[1] + Cbl[1], 0.f));
                A2[j][3] = hpack2(fmaxf(Cbh[2] + Cbl[2], 0.f), fmaxf(Cbh[3] + Cbl[3], 0.f));
            }
        }
        {   // out = nf + h@uW2 + ub2
            #pragma unroll
            for (int np = 0; np < 4; np++) {
                float2 b0v = *(const float2*)(ub2s + np * 8 + 2 * m);
                float2 b1v = *(const float2*)(ub2s + (np + 4) * 8 + 2 * m);
                float C0h[4] = {b0v.x, b0v.y, b0v.x, b0v.y}, C0l[4] = {0,0,0,0};
                float C1h[4] = {b1v.x, b1v.y, b1v.x, b1v.y}, C1l[4] = {0,0,0,0};
                #pragma unroll
                for (int kc = 0; kc < 8; kc++) {
                    uint4 b0 = *(const uint4*)(smem + NOFF_BU2 + (((kc * 8 + np) * 32) + lane) * 16);
                    uint4 b1 = *(const uint4*)(smem + NOFF_BU2 + (((kc * 8 + np + 4) * 32) + lane) * 16);
                    mma2s(C0h, C0l, A2[kc], b0);
                    mma2s(C1h, C1l, A2[kc], b1);
                }
                float2 r00 = __ldg((const float2*)(nf + (size_t)n0 * 64 + np * 8 + 2 * m));
                float2 r10 = __ldg((const float2*)(nf + (size_t)n1 * 64 + np * 8 + 2 * m));
                float2 r01 = __ldg((const float2*)(nf + (size_t)n0 * 64 + (np + 4) * 8 + 2 * m));
                float2 r11 = __ldg((const float2*)(nf + (size_t)n1 * 64 + (np + 4) * 8 + 2 * m));
                *(float2*)(out_node + (size_t)n0 * 64 + np * 8 + 2 * m) =
                    make_float2(r00.x + C0h[0] + C0l[0], r00.y + C0h[1] + C0l[1]);
                *(float2*)(out_node + (size_t)n1 * 64 + np * 8 + 2 * m) =
                    make_float2(r10.x + C0h[2] + C0l[2], r10.y + C0h[3] + C0l[3]);
                *(float2*)(out_node + (size_t)n0 * 64 + (np + 4) * 8 + 2 * m) =
                    make_float2(r01.x + C1h[0] + C1l[0], r01.y + C1h[1] + C1l[1]);
                *(float2*)(out_node + (size_t)n1 * 64 + (np + 4) * 8 + 2 * m) =
                    make_float2(r11.x + C1h[2] + C1l[2], r11.y + C1h[3] + C1l[3]);
            }
        }
    }
}

// ---------------------------------------------------------------------------
// Edge kernel: 12 warps, fp16 activations, fp16-split weights (2-pass).
// ---------------------------------------------------------------------------
__global__ __launch_bounds__(TPB_E, 1)
void edge_mlp_kernel(const float* __restrict__ ef,
                     const float* __restrict__ mW1, const float* __restrict__ mb1,
                     const float* __restrict__ mW2, const float* __restrict__ mb2,
                     const float* __restrict__ mW3, const float* __restrict__ mb3,
                     const int*   __restrict__ eidx,
                     float* __restrict__ agg)
{
    extern __shared__ char smem[];
    const int tid  = threadIdx.x;
    const int w    = tid >> 5;
    const int lane = tid & 31;
    const int m    = lane & 3;
    const int qrow = lane >> 2;

    STAGE_FRAGS(OFF_W1, 2, 16, KR_W1E, mW1, 128, TPB_E)
    STAGE_FRAGS(OFF_W2, 8, 16, KR_ID,  mW2, 128, TPB_E)
    STAGE_FRAGS(OFF_W3, 8, 8,  KR_ID,  mW3, 64,  TPB_E)
    float* b1s = (float*)(smem + OFF_B1);
    float* b2s = (float*)(smem + OFF_B2);
    float* b3s = (float*)(smem + OFF_B3);
    if (tid < 128) { b1s[tid] = mb1[tid]; b2s[tid] = mb2[tid]; }
    if (tid < 64)  { b3s[tid] = mb3[tid]; }
    __syncthreads();

    float* pq = (float*)(smem + OFF_PQ + w * PQ_WARP_BYTES);   // [16][PQ_STRIDE]
    const float4 bv1 = ((const float4*)b1s)[lane];

    const int gw = blockIdx.x * NW_E + w;
    const int gstride = gridDim.x * NW_E;

    for (int wt = gw; wt < N_WT_EDGE; wt += gstride) {
        const int base_e = wt * 16;

        int2 se = make_int2(0, 0);
        if (lane < 16) se = ((const int2*)eidx)[base_e + lane];
        __syncwarp();    // also fences pq/msg reuse from previous tile

        // ---- prefetch ef (K=32) ----
        const float* e0p = ef + (size_t)(base_e + qrow) * 32;
        const float* e1p = ef + (size_t)(base_e + qrow + 8) * 32;
        float2 v00 = __ldg((const float2*)(e0p + 2 * m));
        float2 v01 = __ldg((const float2*)(e0p + 2 * m + 8));
        float2 v02 = __ldg((const float2*)(e0p + 2 * m + 16));
        float2 v03 = __ldg((const float2*)(e0p + 2 * m + 24));
        float2 v10 = __ldg((const float2*)(e1p + 2 * m));
        float2 v11 = __ldg((const float2*)(e1p + 2 * m + 8));
        float2 v12 = __ldg((const float2*)(e1p + 2 * m + 16));
        float2 v13 = __ldg((const float2*)(e1p + 2 * m + 24));

        // ---- stage PQ = P[src] + Q[dst] + b1 into warp-private smem ----
        #pragma unroll 4
        for (int r = 0; r < 16; r++) {
            int sr = __shfl_sync(0xffffffffu, se.x, r);
            int dr = __shfl_sync(0xffffffffu, se.y, r);
            float4 pv = __ldg((const float4*)g_P + (size_t)sr * 32 + lane);
            float4 qv = __ldg((const float4*)g_Q + (size_t)dr * 32 + lane);
            float4 o;
            o.x = pv.x + qv.x + bv1.x; o.y = pv.y + qv.y + bv1.y;
            o.z = pv.z + qv.z + bv1.z; o.w = pv.w + qv.w + bv1.w;
            *(float4*)(pq + r * PQ_STRIDE + lane * 4) = o;
        }
        __syncwarp();

        // ---- A1 fragments (single fp16) ----
        uint32_t A1[2][4];
        A1[0][0] = hpack2(v00.x, v00.y);
        A1[0][1] = hpack2(v10.x, v10.y);
        A1[0][2] = hpack2(v01.x, v01.y);
        A1[0][3] = hpack2(v11.x, v11.y);
        A1[1][0] = hpack2(v02.x, v02.y);
        A1[1][1] = hpack2(v12.x, v12.y);
        A1[1][2] = hpack2(v03.x, v03.y);
        A1[1][3] = hpack2(v13.x, v13.y);

        // ---- L1 (4 nc-chains x Ch/Cl): Ch init = PQ, Cl = 0 ----
        uint32_t A2[8][4];
        #pragma unroll
        for (int j = 0; j < 4; j++) {
            int j2 = j + 4;
            float Ch[4][4], Cl[4][4];
            {
                float2 pa0 = *(const float2*)(pq + qrow * PQ_STRIDE + 16 * j + 2 * m);
                float2 pa1 = *(const float2*)(pq + (qrow + 8) * PQ_STRIDE + 16 * j + 2 * m);
                float2 pb0 = *(const float2*)(pq + qrow * PQ_STRIDE + 16 * j + 8 + 2 * m);
                float2 pb1 = *(const float2*)(pq + (qrow + 8) * PQ_STRIDE + 16 * j + 8 + 2 * m);
                float2 qa0 = *(const float2*)(pq + qrow * PQ_STRIDE + 16 * j2 + 2 * m);
                float2 qa1 = *(const float2*)(pq + (qrow + 8) * PQ_STRIDE + 16 * j2 + 2 * m);
                float2 qb0 = *(const float2*)(pq + qrow * PQ_STRIDE + 16 * j2 + 8 + 2 * m);
                float2 qb1 = *(const float2*)(pq + (qrow + 8) * PQ_STRIDE + 16 * j2 + 8 + 2 * m);
                Ch[0][0] = pa0.x; Ch[0][1] = pa0.y; Ch[0][2] = pa1.x; Ch[0][3] = pa1.y;
                Ch[1][0] = pb0.x; Ch[1][1] = pb0.y; Ch[1][2] = pb1.x; Ch[1][3] = pb1.y;
                Ch[2][0] = qa0.x; Ch[2][1] = qa0.y; Ch[2][2] = qa1.x; Ch[2][3] = qa1.y;
                Ch[3][0] = qb0.x; Ch[3][1] = qb0.y; Ch[3][2] = qb1.x; Ch[3][3] = qb1.y;
                #pragma unroll
                for (int c = 0; c < 4; c++)
                    #pragma unroll
                    for (int i = 0; i < 4; i++) Cl[c][i] = 0.f;
            }
            #pragma unroll
            for (int kc = 0; kc < 2; kc++) {
                uint4 b0 = *(const uint4*)(smem + OFF_W1 + (((kc * 16 + 2 * j) * 32) + lane) * 16);
                uint4 b1 = *(const uint4*)(smem + OFF_W1 + (((kc * 16 + 2 * j + 1) * 32) + lane) * 16);
                uint4 b2 = *(const uint4*)(smem + OFF_W1 + (((kc * 16 + 2 * j2) * 32) + lane) * 16);
                uint4 b3 = *(const uint4*)(smem + OFF_W1 + (((kc * 16 + 2 * j2 + 1) * 32) + lane) * 16);
                mma2s(Ch[0], Cl[0], A1[kc], b0);
                mma2s(Ch[1], Cl[1], A1[kc], b1);
                mma2s(Ch[2], Cl[2], A1[kc], b2);
                mma2s(Ch[3], Cl[3], A1[kc], b3);
            }
            A2[j][0]  = hpack2(fmaxf(Ch[0][0] + Cl[0][0], 0.f), fmaxf(Ch[0][1] + Cl[0][1], 0.f));
            A2[j][1]  = hpack2(fmaxf(Ch[0][2] + Cl[0][2], 0.f), fmaxf(Ch[0][3] + Cl[0][3], 0.f));
            A2[j][2]  = hpack2(fmaxf(Ch[1][0] + Cl[1][0], 0.f), fmaxf(Ch[1][1] + Cl[1][1], 0.f));
            A2[j][3]  = hpack2(fmaxf(Ch[1][2] + Cl[1][2], 0.f), fmaxf(Ch[1][3] + Cl[1][3], 0.f));
            A2[j2][0] = hpack2(fmaxf(Ch[2][0] + Cl[2][0], 0.f), fmaxf(Ch[2][1] + Cl[2][1], 0.f));
            A2[j2][1] = hpack2(fmaxf(Ch[2][2] + Cl[2][2], 0.f), fmaxf(Ch[2][3] + Cl[2][3], 0.f));
            A2[j2][2] = hpack2(fmaxf(Ch[3][0] + Cl[3][0], 0.f), fmaxf(Ch[3][1] + Cl[3][1], 0.f));
            A2[j2][3] = hpack2(fmaxf(Ch[3][2] + Cl[3][2], 0.f), fmaxf(Ch[3][3] + Cl[3][3], 0.f));
        }

        // ---- L2 (4 nc-chains x Ch/Cl): Ch init = b2 ----
        uint32_t A3[8][4];
        #pragma unroll
        for (int j = 0; j < 4; j++) {
            int j2 = j + 4;
            float Ch[4][4], Cl[4][4];
            {
                float2 ba2 = *(const float2*)(b2s + (2 * j) * 8 + 2 * m);
                float2 bb2 = *(const float2*)(b2s + (2 * j + 1) * 8 + 2 * m);
                float2 bc2 = *(const float2*)(b2s + (2 * j2) * 8 + 2 * m);
                float2 bd2 = *(const float2*)(b2s + (2 * j2 + 1) * 8 + 2 * m);
                Ch[0][0] = ba2.x; Ch[0][1] = ba2.y; Ch[0][2] = ba2.x; Ch[0][3] = ba2.y;
                Ch[1][0] = bb2.x; Ch[1][1] = bb2.y; Ch[1][2] = bb2.x; Ch[1][3] = bb2.y;
                Ch[2][0] = bc2.x; Ch[2][1] = bc2.y; Ch[2][2] = bc2.x; Ch[2][3] = bc2.y;
                Ch[3][0] = bd2.x; Ch[3][1] = bd2.y; Ch[3][2] = bd2.x; Ch[3][3] = bd2.y;
                #pragma unroll
                for (int c = 0; c < 4; c++)
                    #pragma unroll
                    for (int i = 0; i < 4; i++) Cl[c][i] = 0.f;
            }
            #pragma unroll
            for (int kc = 0; kc < 8; kc++) {
                uint4 b0 = *(const uint4*)(smem + OFF_W2 + (((kc * 16 + 2 * j) * 32) + lane) * 16);
                uint4 b1 = *(const uint4*)(smem + OFF_W2 + (((kc * 16 + 2 * j + 1) * 32) + lane) * 16);
                uint4 b2 = *(const uint4*)(smem + OFF_W2 + (((kc * 16 + 2 * j2) * 32) + lane) * 16);
                uint4 b3 = *(const uint4*)(smem + OFF_W2 + (((kc * 16 + 2 * j2 + 1) * 32) + lane) * 16);
                mma2s(Ch[0], Cl[0], A2[kc], b0);
                mma2s(Ch[1], Cl[1], A2[kc], b1);
                mma2s(Ch[2], Cl[2], A2[kc], b2);
                mma2s(Ch[3], Cl[3], A2[kc], b3);
            }
            A3[j][0]  = hpack2(fmaxf(Ch[0][0] + Cl[0][0], 0.f), fmaxf(Ch[0][1] + Cl[0][1], 0.f));
            A3[j][1]  = hpack2(fmaxf(Ch[0][2] + Cl[0][2], 0.f), fmaxf(Ch[0][3] + Cl[0][3], 0.f));
            A3[j][2]  = hpack2(fmaxf(Ch[1][0] + Cl[1][0], 0.f), fmaxf(Ch[1][1] + Cl[1][1], 0.f));
            A3[j][3]  = hpack2(fmaxf(Ch[1][2] + Cl[1][2], 0.f), fmaxf(Ch[1][3] + Cl[1][3], 0.f));
            A3[j2][0] = hpack2(fmaxf(Ch[2][0] + Cl[2][0], 0.f), fmaxf(Ch[2][1] + Cl[2][1], 0.f));
            A3[j2][1] = hpack2(fmaxf(Ch[2][2] + Cl[2][2], 0.f), fmaxf(Ch[2][3] + Cl[2][3], 0.f));
            A3[j2][2] = hpack2(fmaxf(Ch[3][0] + Cl[3][0], 0.f), fmaxf(Ch[3][1] + Cl[3][1], 0.f));
            A3[j2][3] = hpack2(fmaxf(Ch[3][2] + Cl[3][2], 0.f), fmaxf(Ch[3][3] + Cl[3][3], 0.f));
        }

        // ---- L3 (4 nc-chains x Ch/Cl): Ch init = b3; -> msg ----
        float* msg = pq;
        __syncwarp();   // pq reads (L1 init) complete before msg overwrite
        #pragma unroll
        for (int nc = 0; nc < 2; nc++) {
            float Ch[4][4], Cl[4][4];
            {
                float2 b0v = *(const float2*)(b3s + nc * 8 + 2 * m);
                float2 b1v = *(const float2*)(b3s + (nc + 2) * 8 + 2 * m);
                float2 b2v = *(const float2*)(b3s + (nc + 4) * 8 + 2 * m);
                float2 b3v = *(const float2*)(b3s + (nc + 6) * 8 + 2 * m);
                Ch[0][0] = b0v.x; Ch[0][1] = b0v.y; Ch[0][2] = b0v.x; Ch[0][3] = b0v.y;
                Ch[1][0] = b1v.x; Ch[1][1] = b1v.y; Ch[1][2] = b1v.x; Ch[1][3] = b1v.y;
                Ch[2][0] = b2v.x; Ch[2][1] = b2v.y; Ch[2][2] = b2v.x; Ch[2][3] = b2v.y;
                Ch[3][0] = b3v.x; Ch[3][1] = b3v.y; Ch[3][2] = b3v.x; Ch[3][3] = b3v.y;
                #pragma unroll
                for (int c = 0; c < 4; c++)
                    #pragma unroll
                    for (int i = 0; i < 4; i++) Cl[c][i] = 0.f;
            }
            #pragma unroll
            for (int kc = 0; kc < 8; kc++) {
                uint4 b0 = *(const uint4*)(smem + OFF_W3 + (((kc * 8 + nc) * 32) + lane) * 16);
                uint4 b1 = *(const uint4*)(smem + OFF_W3 + (((kc * 8 + nc + 2) * 32) + lane) * 16);
                uint4 b2 = *(const uint4*)(smem + OFF_W3 + (((kc * 8 + nc + 4) * 32) + lane) * 16);
                uint4 b3 = *(const uint4*)(smem + OFF_W3 + (((kc * 8 + nc + 6) * 32) + lane) * 16);
                mma2s(Ch[0], Cl[0], A3[kc], b0);
                mma2s(Ch[1], Cl[1], A3[kc], b1);
                mma2s(Ch[2], Cl[2], A3[kc], b2);
                mma2s(Ch[3], Cl[3], A3[kc], b3);
            }
            #pragma unroll
            for (int c = 0; c < 4; c++) {
                int n8 = 8 * (nc + 2 * c);
                *(float2*)(msg + qrow * 72 + n8 + 2 * m) =
                    make_float2(Ch[c][0] + Cl[c][0], Ch[c][1] + Cl[c][1]);
                *(float2*)(msg + (qrow + 8) * 72 + n8 + 2 * m) =
                    make_float2(Ch[c][2] + Cl[c][2], Ch[c][3] + Cl[c][3]);
            }
        }
        __syncwarp();

        // ---- scatter: 16 edges x 16 float4 atomics ----
        #pragma unroll
        for (int it = 0; it < 8; it++) {
            int slot = it * 32 + lane;
            int e = slot >> 4, q = slot & 15;
            float4 v = *(const float4*)(msg + e * 72 + q * 4);
            int dn = __shfl_sync(0xffffffffu, se.y, e);
            atomicAdd(((float4*)(agg + (size_t)dn * 64)) + q, v);
        }
    }
}

extern "C" void kernel_launch(void* const* d_in, const int* in_sizes, int n_in,
                              void* d_out, int out_size)
{
    const float* nf  = (const float*)d_in[0];
    const float* ef  = (const float*)d_in[1];
    const float* stx = (const float*)d_in[2];
    const float* mW1 = (const float*)d_in[3];
    const float* mb1 = (const float*)d_in[4];
    const float* mW2 = (const float*)d_in[5];
    const float* mb2 = (const float*)d_in[6];
    const float* mW3 = (const float*)d_in[7];
    const float* mb3 = (const float*)d_in[8];
    const float* uW1 = (const float*)d_in[9];
    const float* ub1 = (const float*)d_in[10];
    const float* uW2 = (const float*)d_in[11];
    const float* ub2 = (const float*)d_in[12];
    const int*  eidx = (const int*)d_in[13];

    float* out_node = (float*)d_out;
    float* agg      = out_node + (size_t)N_NODES_C * 64;

    cudaFuncSetAttribute(edge_mlp_kernel,
                         cudaFuncAttributeMaxDynamicSharedMemorySize, EDGE_SMEM_BYTES);
    cudaFuncSetAttribute(node_fused_kernel,
                         cudaFuncAttributeMaxDynamicSharedMemorySize, NODEF_SMEM_BYTES);

    int dev = 0;
    cudaGetDevice(&dev);
    int sms = 148;
    cudaDeviceGetAttribute(&sms, cudaDevAttrMultiProcessorCount, dev);

    node_fused_kernel<<<sms, TPB_N, NODEF_SMEM_BYTES>>>(nf, stx, mW1, uW1, ub1, uW2, ub2,
                                                        out_node, agg);
    edge_mlp_kernel<<<sms, TPB_E, EDGE_SMEM_BYTES>>>(ef, mW1, mb1, mW2, mb2,
                                                     mW3, mb3, eidx, agg);
}